// round 1
// baseline (speedup 1.0000x reference)
#include <cuda_runtime.h>

// Problem constants (fixed shapes from reference)
#define B_   4
#define CIN  256
#define CO_  64
#define N_   576   // H*W = 24*24, both Nk and Nq
#define CV_  256

// Scratch (device globals — no allocation allowed)
__device__ float g_kp[B_ * N_ * CO_];          // (B, Nk, CO)
__device__ float g_qp[B_ * N_ * CO_];          // (B, Nq, CO)
__device__ float g_attn[B_ * N_ * N_];         // (B, Nk, Nq)

// ---------- packed fp32x2 helpers (Blackwell FFMA2 path) ----------
__device__ __forceinline__ unsigned long long pack2(float lo, float hi) {
    unsigned long long r;
    asm("mov.b64 %0, {%1, %2};" : "=l"(r) : "f"(lo), "f"(hi));
    return r;
}
__device__ __forceinline__ void unpack2(unsigned long long v, float& lo, float& hi) {
    asm("mov.b64 {%0, %1}, %2;" : "=f"(lo), "=f"(hi) : "l"(v));
}
__device__ __forceinline__ unsigned long long ffma2(unsigned long long a,
                                                    unsigned long long b,
                                                    unsigned long long c) {
    unsigned long long d;
    asm("fma.rn.f32x2 %0, %1, %2, %3;" : "=l"(d) : "l"(a), "l"(b), "l"(c));
    return d;
}
__device__ __forceinline__ float tanhfast(float x) {
    float y;
    asm("tanh.approx.f32 %0, %1;" : "=f"(y) : "f"(x));
    return y;
}

// ============================================================================
// Kernel A: 1x1-conv projections.  k_[b,n,c] = sum_ch key[b,ch,n]*Wk[c,ch]+bk[c]
// grid (18 n-tiles of 32, B, 2{k,q}), 256 threads.
// ============================================================================
__global__ void __launch_bounds__(256) proj_kernel(
    const float* __restrict__ key, const float* __restrict__ query,
    const float* __restrict__ Wk,  const float* __restrict__ bk,
    const float* __restrict__ Wq,  const float* __restrict__ bq)
{
    const int kind = blockIdx.z;
    const float* X    = kind ? query : key;    // (B, CIN, N)
    const float* W    = kind ? Wq    : Wk;     // (CO, CIN)
    const float* bias = kind ? bq    : bk;     // (CO)
    float* outp       = kind ? g_qp  : g_kp;   // (B, N, CO)

    const int b  = blockIdx.y;
    const int n0 = blockIdx.x * 32;

    __shared__ float sX[64][32];    // [ch][n]  (rows 128B: LDS.64 aligned, reads broadcast)
    __shared__ float sW[64][65];    // [c][ch]  padded -> conflict-free strided reads

    const int t  = threadIdx.x;
    const int c  = t & 63;
    const int ng = t >> 6;          // 0..3 : this thread owns n = ng*8 .. ng*8+7

    const float bv = bias[c];
    unsigned long long acc[4];
    #pragma unroll
    for (int p = 0; p < 4; p++) acc[p] = pack2(bv, 0.0f), acc[p] = (p == 0) ? pack2(bv, bv) : pack2(bv, bv);
    #pragma unroll
    for (int p = 0; p < 4; p++) acc[p] = pack2(bv, bv);

    for (int ch0 = 0; ch0 < CIN; ch0 += 64) {
        // load X chunk: 64 ch x 32 n (coalesced over n)
        {
            const int n  = t & 31;
            const int cb = t >> 5;
            #pragma unroll
            for (int i = 0; i < 8; i++) {
                const int ch = cb + i * 8;
                sX[ch][n] = X[((size_t)(b * CIN + ch0 + ch)) * N_ + n0 + n];
            }
        }
        // load W chunk: 64 c x 64 ch (coalesced over ch)
        {
            const int ch = t & 63;
            const int cb = t >> 6;
            #pragma unroll
            for (int i = 0; i < 16; i++) {
                const int cr = cb + i * 4;
                sW[cr][ch] = W[cr * CIN + ch0 + ch];
            }
        }
        __syncthreads();

        #pragma unroll 16
        for (int ch = 0; ch < 64; ch++) {
            const float w = sW[c][ch];
            const unsigned long long ww = pack2(w, w);
            #pragma unroll
            for (int p = 0; p < 4; p++) {
                const unsigned long long x2 =
                    *(const unsigned long long*)&sX[ch][ng * 8 + 2 * p];
                acc[p] = ffma2(x2, ww, acc[p]);
            }
        }
        __syncthreads();
    }

    // store: out[(b*N + n)*CO + c], lanes write consecutive c -> coalesced
    #pragma unroll
    for (int p = 0; p < 4; p++) {
        float lo, hi;
        unpack2(acc[p], lo, hi);
        const int n = n0 + ng * 8 + 2 * p;
        outp[((size_t)b * N_ + n) * CO_ + c]     = lo;
        outp[((size_t)b * N_ + n + 1) * CO_ + c] = hi;
    }
}

// ============================================================================
// Kernel B: attn[b,k,q] = sigmoid( bf + sum_c tanh(kp[b,k,c]+qp[b,q,c])*wf[c] )
// grid (18 q-tiles, 18 k-tiles, B), 256 threads; thread = 1 k x 4 q. MUFU-bound.
// ============================================================================
__global__ void __launch_bounds__(256) attn_kernel(
    const float* __restrict__ wf, const float* __restrict__ bfp)
{
    const int b  = blockIdx.z;
    const int k0 = blockIdx.y * 32;
    const int q0 = blockIdx.x * 32;

    __shared__ float sk[32][65];
    __shared__ float sq[32][65];
    __shared__ float swf[64];

    const int t = threadIdx.x;
    {
        const int c  = t & 63;
        const int rb = t >> 6;
        #pragma unroll
        for (int i = 0; i < 8; i++) {
            const int r = rb + i * 4;
            sk[r][c] = g_kp[((size_t)b * N_ + k0 + r) * CO_ + c];
            sq[r][c] = g_qp[((size_t)b * N_ + q0 + r) * CO_ + c];
        }
    }
    if (t < 64) swf[t] = wf[t];
    __syncthreads();

    const int q4 = (t & 7) * 4;     // first of 4 q's
    const int k  = t >> 3;          // 0..31

    const float* __restrict__ skr = sk[k];
    const float* __restrict__ s0  = sq[q4 + 0];
    const float* __restrict__ s1  = sq[q4 + 1];
    const float* __restrict__ s2  = sq[q4 + 2];
    const float* __restrict__ s3  = sq[q4 + 3];

    const float bf = bfp[0];
    float a0 = bf, a1 = bf, a2 = bf, a3 = bf;

    #pragma unroll 16
    for (int c = 0; c < 64; c++) {
        const float kv = skr[c];
        const float w  = swf[c];
        a0 = fmaf(tanhfast(kv + s0[c]), w, a0);
        a1 = fmaf(tanhfast(kv + s1[c]), w, a1);
        a2 = fmaf(tanhfast(kv + s2[c]), w, a2);
        a3 = fmaf(tanhfast(kv + s3[c]), w, a3);
    }

    // sigmoid(x) = 0.5*tanh(0.5x)+0.5
    float4 r4;
    r4.x = fmaf(0.5f, tanhfast(0.5f * a0), 0.5f);
    r4.y = fmaf(0.5f, tanhfast(0.5f * a1), 0.5f);
    r4.z = fmaf(0.5f, tanhfast(0.5f * a2), 0.5f);
    r4.w = fmaf(0.5f, tanhfast(0.5f * a3), 0.5f);

    *(float4*)&g_attn[((size_t)b * N_ + k0 + k) * N_ + q0 + q4] = r4;
}

// ============================================================================
// Kernel C: out[b,c,q] = sum_k value[b,c,k] * attn[b,k,q]
// grid (9 q-tiles of 64, 4 c-tiles of 64, B), 256 threads; thread = 4c x 4q,
// accumulators packed over q as f32x2 (FFMA2).
// ============================================================================
__global__ void __launch_bounds__(256) out_kernel(
    const float* __restrict__ value, float* __restrict__ out)
{
    const int b  = blockIdx.z;
    const int c0 = blockIdx.y * 64;
    const int q0 = blockIdx.x * 64;

    __shared__ float sV[64][33];    // [c][k], padded: conflict-free writes, broadcast reads
    __shared__ float sA[32][64];    // [k][q], 16B-aligned rows for LDS.128

    const int t  = threadIdx.x;
    const int qg = t & 15;          // q = qg*4 .. +3
    const int cg = t >> 4;          // 0..15, c = cg*4 .. +3

    unsigned long long acc[4][2];
    #pragma unroll
    for (int i = 0; i < 4; i++) { acc[i][0] = 0ull; acc[i][1] = 0ull; }

    for (int k0 = 0; k0 < N_; k0 += 32) {
        // load V tile: 64 c x 32 k (coalesced over k)
        {
            const int kk = t & 31;
            const int cb = t >> 5;
            #pragma unroll
            for (int i = 0; i < 8; i++) {
                const int cr = cb + i * 8;
                sV[cr][kk] = value[((size_t)(b * CV_ + c0 + cr)) * N_ + k0 + kk];
            }
        }
        // load A tile: 32 k x 64 q (coalesced over q)
        {
            const int q  = t & 63;
            const int kb = t >> 6;
            #pragma unroll
            for (int i = 0; i < 8; i++) {
                const int kr = kb + i * 4;
                sA[kr][q] = g_attn[((size_t)b * N_ + k0 + kr) * N_ + q0 + q];
            }
        }
        __syncthreads();

        #pragma unroll 8
        for (int kk = 0; kk < 32; kk++) {
            const ulonglong2 a2 = *(const ulonglong2*)&sA[kk][qg * 4];
            #pragma unroll
            for (int i = 0; i < 4; i++) {
                const float v = sV[cg * 4 + i][kk];
                const unsigned long long vv = pack2(v, v);
                acc[i][0] = ffma2(vv, a2.x, acc[i][0]);
                acc[i][1] = ffma2(vv, a2.y, acc[i][1]);
            }
        }
        __syncthreads();
    }

    #pragma unroll
    for (int i = 0; i < 4; i++) {
        float o0, o1, o2, o3;
        unpack2(acc[i][0], o0, o1);
        unpack2(acc[i][1], o2, o3);
        *(float4*)&out[((size_t)(b * CV_ + c0 + cg * 4 + i)) * N_ + q0 + qg * 4] =
            make_float4(o0, o1, o2, o3);
    }
}

// ============================================================================
extern "C" void kernel_launch(void* const* d_in, const int* in_sizes, int n_in,
                              void* d_out, int out_size)
{
    const float* key   = (const float*)d_in[0];
    const float* query = (const float*)d_in[1];
    const float* value = (const float*)d_in[2];
    const float* Wk    = (const float*)d_in[3];
    const float* bk    = (const float*)d_in[4];
    const float* Wq    = (const float*)d_in[5];
    const float* bq    = (const float*)d_in[6];
    const float* wf    = (const float*)d_in[7];
    const float* bf    = (const float*)d_in[8];
    float* out = (float*)d_out;

    proj_kernel<<<dim3(N_ / 32, B_, 2), 256>>>(key, query, Wk, bk, Wq, bq);
    attn_kernel<<<dim3(N_ / 32, N_ / 32, B_), 256>>>(wf, bf);
    out_kernel<<<dim3(N_ / 64, CV_ / 64, B_), 256>>>(value, out);
}